// round 12
// baseline (speedup 1.0000x reference)
#include <cuda_runtime.h>
#include <cuda_bf16.h>
#include <cstdint>

#define GV 1024
#define GB 128
#define NN (GB * GV)          // 131072 columns (channel-major)
#define KORD 5
#define CKP 960               // padded K stride for split weights

// ---------------- scratch (device globals; no allocation) ----------------
__device__ float g_acta[(size_t)192 * NN];   // activation ping
__device__ float g_actb[(size_t)192 * NN];   // activation pong
__device__ float g_bn_s[192];
__device__ float g_bn_t[192];
__device__ double g_dsum[192];
__device__ double g_dsq[192];
__device__ __nv_bfloat16 g_wh[192 * CKP];    // W hi plane [F][960]
__device__ __nv_bfloat16 g_wl[192 * CKP];    // W lo plane [F][960]

// ---------------- helpers ----------------
__device__ __forceinline__ uint32_t smem_u32(const void* p) {
    uint32_t a;
    asm("{ .reg .u64 t; cvta.to.shared.u64 t, %1; cvt.u32.u64 %0, t; }" : "=r"(a) : "l"(p));
    return a;
}

__device__ __forceinline__ void mma_bf16(float* d, const uint32_t* a, const uint32_t* b) {
    asm volatile(
        "mma.sync.aligned.m16n8k16.row.col.f32.bf16.bf16.f32 "
        "{%0,%1,%2,%3}, {%4,%5,%6,%7}, {%8,%9}, {%0,%1,%2,%3};"
        : "+f"(d[0]), "+f"(d[1]), "+f"(d[2]), "+f"(d[3])
        : "r"(a[0]), "r"(a[1]), "r"(a[2]), "r"(a[3]), "r"(b[0]), "r"(b[1]));
}

#define LDSM_X4(r0, r1, r2, r3, addr) \
    asm volatile("ldmatrix.sync.aligned.m8n8.x4.shared.b16 {%0,%1,%2,%3}, [%4];" \
                 : "=r"(r0), "=r"(r1), "=r"(r2), "=r"(r3) : "r"(addr))
#define LDSM_X4T(r0, r1, r2, r3, addr) \
    asm volatile("ldmatrix.sync.aligned.m8n8.x4.trans.shared.b16 {%0,%1,%2,%3}, [%4];" \
                 : "=r"(r0), "=r"(r1), "=r"(r2), "=r"(r3) : "r"(addr))

#define CP_ASYNC16(dst, src) \
    asm volatile("cp.async.ca.shared.global [%0], [%1], 16;" :: "r"(dst), "l"(src) : "memory")
#define CP_COMMIT() asm volatile("cp.async.commit_group;" ::: "memory")
#define CP_WAIT0()  asm volatile("cp.async.wait_group 0;" ::: "memory")
#define CP_WAIT1()  asm volatile("cp.async.wait_group 1;" ::: "memory")
#define STS16(addr, v) \
    asm volatile("st.shared.b16 [%0], %1;" :: "r"(addr), "h"(v))

// ---------------- W split + BN finalize (prev layer) + accumulator zeroing ----------------
__global__ void wsplit_bn(const float* __restrict__ W, int F, int CK,
                          const float* __restrict__ gamma_p, const float* __restrict__ beta_p,
                          int Fprev, int do_bn) {
    int idx = blockIdx.x * 256 + threadIdx.x;
    if (blockIdx.x == 0 && threadIdx.x < 192) {
        int f = threadIdx.x;
        if (do_bn && f < Fprev) {
            double mean = g_dsum[f] / (double)NN;
            double var  = g_dsq[f] / (double)NN - mean * mean;
            float sc = gamma_p[f] * rsqrtf((float)var + 1e-5f);
            g_bn_s[f] = sc;
            g_bn_t[f] = beta_p[f] - (float)mean * sc;
        }
        g_dsum[f] = 0.0;
        g_dsq[f]  = 0.0;
    }
    if (idx >= F * CKP) return;
    int k = idx % CKP;
    int f = idx / CKP;
    float v = (k < CK) ? W[(size_t)f * CK + k] : 0.f;
    __nv_bfloat16 h = __float2bfloat16_rn(v);
    g_wh[idx] = h;
    g_wl[idx] = __float2bfloat16_rn(v - __bfloat162float(h));
}

__device__ __forceinline__ float rsd_of(int i, int j) {
    int deg = (i > 0) + (i < 31) + (j > 0) + (j < 31);
    return (deg == 4) ? 0.5f : (deg == 3 ? 0.57735026918962576f : 0.70710678118654752f);
}

// ---------------- fused cheb-expansion + tensor-core GEMM + BN stats ----------------
// CTA: 96m x 128n. Stage = 16 channels = 80 k-rows (5 k16 chunks).
// B-tile generated in-kernel: per warp, 2 channels; 12-grid-row halo window in regs,
// lane j = grid column; stencil recursion T0..T4; center 4 rows -> bf16 hi/lo smem.
#define ROWA 176                       // 80 k * 2B + 16 pad
#define APL (96 * ROWA)                // 16896 per A plane
#define ABUF (2 * APL)                 // 33792 per A buffer (hi+lo)
#define OFF_B (2 * ABUF)               // 67584
#define ROWB2 272                      // 128 n * 2B + 16 pad
#define BPL (80 * ROWB2)               // 21760 per B plane
#define SMEMG (OFF_B + 2 * BPL)        // 111104

__global__ void __launch_bounds__(256, 2)
gemm_fused(const float* __restrict__ in, float* __restrict__ out,
           int C, int F, int layer0) {
    extern __shared__ char smem[];
    const uint32_t sb = smem_u32(smem);

    const int tid  = threadIdx.x;
    const int lane = tid & 31;
    const int wid  = tid >> 5;
    const int wm   = wid & 1;
    const int wn   = wid >> 1;
    const int g    = lane >> 2;
    const int t4   = lane & 3;
    const int l15  = lane & 15;
    const int lhi  = lane >> 4;
    const int j    = lane;              // grid column (0..31)

    const int m0 = blockIdx.x * 96;
    const int by = blockIdx.y;
    const int b  = by >> 3;             // batch
    const int v0 = (by & 7) * 128;      // node offset within batch
    const int i0 = v0 >> 5;             // first grid row of tile (mult of 4)
    const int ns = (C + 15) >> 4;

    float acc[3][4][4];
#pragma unroll
    for (int a = 0; a < 3; a++)
#pragma unroll
        for (int bq = 0; bq < 4; bq++)
#pragma unroll
            for (int c = 0; c < 4; c++) acc[a][bq][c] = 0.f;

    // ---- A loader: 1920 16B chunks per stage ----
    auto load_A = [&](int s) {
        uint32_t dst = sb + (uint32_t)(s & 1) * ABUF;
        int k0 = s * 80;
#pragma unroll
        for (int i = 0; i < 8; i++) {
            int e = tid + 256 * i;
            if (e < 1920) {
                int p = e >= 960;
                int id = e - 960 * p;
                int r = id / 10, q = id - 10 * r;
                const __nv_bfloat16* src =
                    (p ? g_wl : g_wh) + (size_t)(m0 + r) * CKP + k0 + q * 8;
                CP_ASYNC16(dst + p * APL + r * ROWA + q * 16, src);
            }
        }
        CP_COMMIT();
    };

    // ---- stencil: o = L~ t (z-form); rs==0 marks out-of-grid rows, keeping them 0 ----
    auto stencil = [&](float* o, const float* t, const float* rs) {
        float z[12];
#pragma unroll
        for (int r = 0; r < 12; r++) z[r] = rs[r] * t[r];
#pragma unroll
        for (int r = 0; r < 12; r++) {
            float a = 0.f;
            if (r > 0)  a += z[r - 1];
            if (r < 11) a += z[r + 1];
            float zl = __shfl_up_sync(0xffffffffu, z[r], 1);
            float zr = __shfl_down_sync(0xffffffffu, z[r], 1);
            a += (j > 0 ? zl : 0.f) + (j < 31 ? zr : 0.f);
            o[r] = -rs[r] * a;
        }
    };

    auto store_k = [&](int cl, int k, const float* a) {
        int rowB = cl * 5 + k;
        uint32_t base = sb + OFF_B + rowB * ROWB2 + j * 2;
#pragma unroll
        for (int r = 4; r < 8; r++) {
            float v = a[r];
            __nv_bfloat16 h = __float2bfloat16_rn(v);
            __nv_bfloat16 lo = __float2bfloat16_rn(v - __bfloat162float(h));
            uint32_t addr = base + (r - 4) * 64;
            STS16(addr, (uint16_t)__bfloat16_as_ushort(h));
            STS16(addr + BPL, (uint16_t)__bfloat16_as_ushort(lo));
        }
    };

    // ---- B generator: this warp does channels 2*wid, 2*wid+1 of the stage ----
    auto gen_B = [&](int s) {
        int c0 = s * 16;
#pragma unroll
        for (int cc = 0; cc < 2; cc++) {
            int cl = wid * 2 + cc;
            int c  = c0 + cl;
            float tp[12], tc[12], rs[12];
#pragma unroll
            for (int r = 0; r < 12; r++) {
                int iw = i0 - 4 + r;
                bool ingrid = (iw >= 0) && (iw < 32);
                bool ok = ingrid && (c < C);
                float xv = 0.f;
                if (ok) {
                    if (layer0) {
                        xv = in[((size_t)b * C + c) * GV + iw * 32 + j];
                    } else {
                        float a = in[(size_t)c * NN + (size_t)b * GV + iw * 32 + j];
                        xv = fmaxf(fmaf(a, g_bn_s[c], g_bn_t[c]), 0.f);
                    }
                }
                tp[r] = xv;
                rs[r] = ingrid ? rsd_of(iw, j) : 0.f;   // FIX: zero weight off-grid
            }
            store_k(cl, 0, tp);
            stencil(tc, tp, rs);          // T1 = L T0
            store_k(cl, 1, tc);
#pragma unroll
            for (int k = 2; k < KORD; k++) {
                float lc[12];
                stencil(lc, tc, rs);
                float tn[12];
#pragma unroll
                for (int r = 0; r < 12; r++) tn[r] = fmaf(2.f, lc[r], -tp[r]);
                store_k(cl, k, tn);
#pragma unroll
                for (int r = 0; r < 12; r++) { tp[r] = tc[r]; tc[r] = tn[r]; }
            }
        }
    };

    // ---- main loop ----
    load_A(0);
    for (int s = 0; s < ns; s++) {
        const bool more = (s + 1 < ns);
        __syncthreads();                  // prior mma done reading B smem
        if (more) load_A(s + 1);
        gen_B(s);
        if (more) { CP_WAIT1(); } else { CP_WAIT0(); }
        __syncthreads();                  // B written, A(s) arrived

        const uint32_t abh = sb + (uint32_t)(s & 1) * ABUF;
        const uint32_t abl = abh + APL;
#pragma unroll
        for (int q = 0; q < 5; q++) {
            uint32_t ah[3][4], al[3][4];
#pragma unroll
            for (int mf = 0; mf < 3; mf++) {
                int row = wm * 48 + mf * 16 + l15;
                uint32_t qa = (uint32_t)(2 * q + lhi);
                uint32_t addr = abh + row * ROWA + qa * 16;
                LDSM_X4(ah[mf][0], ah[mf][1], ah[mf][2], ah[mf][3], addr);
                LDSM_X4(al[mf][0], al[mf][1], al[mf][2], al[mf][3], addr + (abl - abh));
            }
            uint32_t bh[2][4], bl[2][4];
#pragma unroll
            for (int p = 0; p < 2; p++) {
                int krow = 16 * q + l15;
                int nbyte = wn * 64 + p * 32 + lhi * 16;
                uint32_t addr = sb + OFF_B + krow * ROWB2 + nbyte;
                LDSM_X4T(bh[p][0], bh[p][1], bh[p][2], bh[p][3], addr);
                LDSM_X4T(bl[p][0], bl[p][1], bl[p][2], bl[p][3], addr + BPL);
            }
#pragma unroll
            for (int p = 0; p < 2; p++)
#pragma unroll
                for (int h = 0; h < 2; h++) {
                    int nf = 2 * p + h;
#pragma unroll
                    for (int mf = 0; mf < 3; mf++) {
                        mma_bf16(acc[mf][nf], ah[mf], &bh[p][2 * h]);
                        mma_bf16(acc[mf][nf], al[mf], &bh[p][2 * h]);
                        mma_bf16(acc[mf][nf], ah[mf], &bl[p][2 * h]);
                    }
                }
        }
    }
    __syncthreads();

    // ---- epilogue 1: fragments -> out ----
    const int n0 = by * 128;
#pragma unroll
    for (int mf = 0; mf < 3; mf++) {
        int mrow = m0 + wm * 48 + mf * 16 + g;
#pragma unroll
        for (int nf = 0; nf < 4; nf++) {
            int col = n0 + wn * 32 + nf * 8 + 2 * t4;
            *(float2*)(out + (size_t)mrow * NN + col) =
                make_float2(acc[mf][nf][0], acc[mf][nf][1]);
            *(float2*)(out + (size_t)(mrow + 8) * NN + col) =
                make_float2(acc[mf][nf][2], acc[mf][nf][3]);
        }
    }

    // ---- epilogue 2: fused BN partial stats ----
    float* reds = (float*)smem;          // [96][4]
    float* redq = (float*)smem + 384;    // [96][4]
#pragma unroll
    for (int mf = 0; mf < 3; mf++) {
#pragma unroll
        for (int half = 0; half < 2; half++) {
            float s = 0.f, q = 0.f;
#pragma unroll
            for (int nf = 0; nf < 4; nf++) {
                float v0f = acc[mf][nf][2 * half];
                float v1f = acc[mf][nf][2 * half + 1];
                s += v0f + v1f;
                q += v0f * v0f + v1f * v1f;
            }
            s += __shfl_xor_sync(0xffffffffu, s, 1);
            s += __shfl_xor_sync(0xffffffffu, s, 2);
            q += __shfl_xor_sync(0xffffffffu, q, 1);
            q += __shfl_xor_sync(0xffffffffu, q, 2);
            if (t4 == 0) {
                int row = wm * 48 + mf * 16 + half * 8 + g;
                reds[row * 4 + wn] = s;
                redq[row * 4 + wn] = q;
            }
        }
    }
    __syncthreads();
    if (tid < 96) {
        float s = reds[tid * 4] + reds[tid * 4 + 1] + reds[tid * 4 + 2] + reds[tid * 4 + 3];
        float q = redq[tid * 4] + redq[tid * 4 + 1] + redq[tid * 4 + 2] + redq[tid * 4 + 3];
        atomicAdd(&g_dsum[m0 + tid], (double)s);
        atomicAdd(&g_dsq[m0 + tid],  (double)q);
    }
}

// ---------------- BN finalize (last layer only) ----------------
__global__ void bn_final(const float* __restrict__ gamma, const float* __restrict__ beta, int F) {
    int f = threadIdx.x;
    if (f >= F) return;
    double mean = g_dsum[f] / (double)NN;
    double var  = g_dsq[f] / (double)NN - mean * mean;
    float sc = gamma[f] * rsqrtf((float)var + 1e-5f);
    g_bn_s[f] = sc;
    g_bn_t[f] = beta[f] - (float)mean * sc;
}

// ---------------- classifier ----------------
__global__ void classifier(const float* __restrict__ act,
                           const float* __restrict__ cw, const float* __restrict__ cb,
                           float* __restrict__ out) {
    const int b0   = blockIdx.x * 4;
    const int lane = threadIdx.x & 31;
    const int warp = threadIdx.x >> 5;

    float acc[4][10];
#pragma unroll
    for (int bb = 0; bb < 4; bb++)
#pragma unroll
        for (int o = 0; o < 10; o++) acc[bb][o] = 0.f;

    const int NF = 96 * GV;
    for (int f = threadIdx.x; f < NF; f += 256) {
        int c = f >> 10, v = f & (GV - 1);
        float sc = g_bn_s[c], sh = g_bn_t[c];
        float w[10];
#pragma unroll
        for (int o = 0; o < 10; o++) w[o] = cw[(size_t)o * NF + f];
#pragma unroll
        for (int bb = 0; bb < 4; bb++) {
            float y = act[(size_t)c * NN + (size_t)(b0 + bb) * GV + v];
            float h = fmaxf(fmaf(y, sc, sh), 0.f);
#pragma unroll
            for (int o = 0; o < 10; o++) acc[bb][o] = fmaf(h, w[o], acc[bb][o]);
        }
    }

    __shared__ float part[8][40];
#pragma unroll
    for (int bb = 0; bb < 4; bb++)
#pragma unroll
        for (int o = 0; o < 10; o++) {
            float vsum = acc[bb][o];
#pragma unroll
            for (int off = 16; off > 0; off >>= 1)
                vsum += __shfl_down_sync(0xffffffffu, vsum, off);
            if (lane == 0) part[warp][bb * 10 + o] = vsum;
        }
    __syncthreads();
    if (threadIdx.x < 40) {
        float ssum = 0.f;
#pragma unroll
        for (int wq = 0; wq < 8; wq++) ssum += part[wq][threadIdx.x];
        int bb = threadIdx.x / 10, o = threadIdx.x % 10;
        out[(b0 + bb) * 10 + o] = ssum + cb[o];
    }
}

// ---------------- launch ----------------
extern "C" void kernel_launch(void* const* d_in, const int* in_sizes, int n_in,
                              void* d_out, int out_size) {
    (void)out_size;
    const float* x = (const float*)d_in[0];
    const float* w[7];
    const float* gg[7];
    const float* bb[7];

    if (n_in >= 25 && in_sizes[3] == 96) {  // dict order (w,g,b per layer)
        for (int i = 0; i < 7; i++) {
            w[i]  = (const float*)d_in[2 + 3 * i];
            gg[i] = (const float*)d_in[3 + 3 * i];
            bb[i] = (const float*)d_in[4 + 3 * i];
        }
    } else {                                // signature order
        for (int i = 0; i < 7; i++) {
            w[i]  = (const float*)d_in[2 + i];
            gg[i] = (const float*)d_in[9 + i];
            bb[i] = (const float*)d_in[16 + i];
        }
    }
    const float* clf_w = (const float*)d_in[23];
    const float* clf_b = (const float*)d_in[24];

    static int smem_set = 0;
    if (!smem_set) {
        cudaFuncSetAttribute(gemm_fused, cudaFuncAttributeMaxDynamicSharedMemorySize, SMEMG);
        smem_set = 1;
    }

    float *pa = nullptr, *pb = nullptr;
    cudaGetSymbolAddress((void**)&pa, g_acta);
    cudaGetSymbolAddress((void**)&pb, g_actb);

    const int CIN[7]  = {3, 96, 96, 96, 192, 192, 192};
    const int FOUT[7] = {96, 96, 96, 192, 192, 192, 96};

    for (int l = 0; l < 7; l++) {
        const int C = CIN[l], F = FOUT[l], CK = C * KORD;

        wsplit_bn<<<(F * CKP + 255) / 256, 256>>>(
            w[l], F, CK,
            l ? gg[l - 1] : nullptr, l ? bb[l - 1] : nullptr,
            l ? FOUT[l - 1] : 0, l ? 1 : 0);

        const float* src = (l == 0) ? x : (((l - 1) & 1) ? pb : pa);
        float* dst = (l & 1) ? pb : pa;

        dim3 grid(F / 96, NN / 128);
        gemm_fused<<<grid, 256, SMEMG>>>(src, dst, C, F, l == 0 ? 1 : 0);
    }

    bn_final<<<1, 192>>>(gg[6], bb[6], 96);
    classifier<<<32, 256>>>(pa, clf_w, clf_b, (float*)d_out);  // layer 6 output = pa
}